// round 1
// baseline (speedup 1.0000x reference)
#include <cuda_runtime.h>
#include <math.h>

// Problem constants
#define LSEQ 1024
#define DIM  256
#define BH   32          // B*N = 4*8 heads
#define EDGE_C 112       // N*(N-1)*2
#define NBATCH 4
#define KAPPA 10000.0f

#define H_ELEMS  (BH * LSEQ * DIM)                 // 8,388,608
#define X_ELEMS  (BH * LSEQ * 3)                   // 98,304
#define E_ELEMS  (NBATCH * LSEQ * EDGE_C)          // 458,752
#define X_OFF    H_ELEMS
#define E_OFF    (H_ELEMS + X_ELEMS)

// Scratch (device globals — no allocations allowed)
__device__ float g_TP[H_ELEMS];                    // theta + PE
__device__ float g_Q[H_ELEMS];
__device__ float g_K[H_ELEMS];
__device__ float g_V[H_ELEMS];
__device__ float g_S[(size_t)BH * LSEQ * LSEQ];    // scores / probs (128 MB)

// ---------------------------------------------------------------------------
// Kernel 1: theta_pe = theta + pe(L, 256)
// ---------------------------------------------------------------------------
__global__ void k_theta_pe(const float* __restrict__ theta) {
    int idx = blockIdx.x * 256 + threadIdx.x;      // grid sized exactly
    int i = idx & (DIM - 1);
    int l = (idx >> 8) & (LSEQ - 1);
    float expo = (float)(i & ~1) * (1.0f / (float)DIM);
    float p = powf(KAPPA, expo);
    float ang = (float)l / p;
    float pe = (i & 1) ? cosf(ang) : sinf(ang);
    g_TP[idx] = theta[idx] + pe;
}

// ---------------------------------------------------------------------------
// Kernel 2: QKV projection.  Out[m,e] = sum_d TP[m,d] * W[e,d]
// grid: (4 e-tiles, 512 m-tiles, 3 matrices), 256 threads
// ---------------------------------------------------------------------------
__global__ void k_qkv(const float* __restrict__ Wq,
                      const float* __restrict__ Wk,
                      const float* __restrict__ Wv) {
    __shared__ float As[16][68];   // As[k][m], padded for fp4 align + banks
    __shared__ float Bs[16][68];   // Bs[k][e]

    const float* W = (blockIdx.z == 0) ? Wq : (blockIdx.z == 1) ? Wk : Wv;
    float* Out     = (blockIdx.z == 0) ? g_Q : (blockIdx.z == 1) ? g_K : g_V;

    int tid = threadIdx.x;
    int tx = tid & 15, ty = tid >> 4;
    int m0 = blockIdx.y * 64;
    int e0 = blockIdx.x * 64;

    float acc[4][4] = {};

    for (int k0 = 0; k0 < DIM; k0 += 16) {
        #pragma unroll
        for (int i = 0; i < 4; i++) {
            int idx = tid + i * 256;
            int r = idx >> 4, c = idx & 15;
            As[c][r] = g_TP[(size_t)(m0 + r) * DIM + k0 + c];
            Bs[c][r] = W[(size_t)(e0 + r) * DIM + k0 + c];
        }
        __syncthreads();
        #pragma unroll
        for (int k = 0; k < 16; k++) {
            float4 a = *(const float4*)&As[k][ty << 2];
            float4 b = *(const float4*)&Bs[k][tx << 2];
            acc[0][0] += a.x*b.x; acc[0][1] += a.x*b.y; acc[0][2] += a.x*b.z; acc[0][3] += a.x*b.w;
            acc[1][0] += a.y*b.x; acc[1][1] += a.y*b.y; acc[1][2] += a.y*b.z; acc[1][3] += a.y*b.w;
            acc[2][0] += a.z*b.x; acc[2][1] += a.z*b.y; acc[2][2] += a.z*b.z; acc[2][3] += a.z*b.w;
            acc[3][0] += a.w*b.x; acc[3][1] += a.w*b.y; acc[3][2] += a.w*b.z; acc[3][3] += a.w*b.w;
        }
        __syncthreads();
    }
    #pragma unroll
    for (int i = 0; i < 4; i++)
        #pragma unroll
        for (int j = 0; j < 4; j++)
            Out[(size_t)(m0 + (ty << 2) + i) * DIM + e0 + (tx << 2) + j] = acc[i][j];
}

// ---------------------------------------------------------------------------
// Kernel 3: scores S[q,k] = (Q . K) / 16, lower-triangle tiles only
// grid: (16 kt, 16 qt, 32 bh), 256 threads. Blocks with kt > qt exit.
// ---------------------------------------------------------------------------
__global__ void k_scores() {
    int kt = blockIdx.x, qt = blockIdx.y, bh = blockIdx.z;
    if (kt > qt) return;

    __shared__ float As[16][68];   // As[d][q]
    __shared__ float Bs[16][68];   // Bs[d][k]

    const float* Qp = g_Q + (size_t)bh * LSEQ * DIM;
    const float* Kp = g_K + (size_t)bh * LSEQ * DIM;
    float* S        = g_S + (size_t)bh * LSEQ * LSEQ;

    int tid = threadIdx.x;
    int tx = tid & 15, ty = tid >> 4;
    int q0 = qt * 64, c0 = kt * 64;

    float acc[4][4] = {};

    for (int k0 = 0; k0 < DIM; k0 += 16) {
        #pragma unroll
        for (int i = 0; i < 4; i++) {
            int idx = tid + i * 256;
            int r = idx >> 4, c = idx & 15;
            As[c][r] = Qp[(size_t)(q0 + r) * DIM + k0 + c];
            Bs[c][r] = Kp[(size_t)(c0 + r) * DIM + k0 + c];
        }
        __syncthreads();
        #pragma unroll
        for (int k = 0; k < 16; k++) {
            float4 a = *(const float4*)&As[k][ty << 2];
            float4 b = *(const float4*)&Bs[k][tx << 2];
            acc[0][0] += a.x*b.x; acc[0][1] += a.x*b.y; acc[0][2] += a.x*b.z; acc[0][3] += a.x*b.w;
            acc[1][0] += a.y*b.x; acc[1][1] += a.y*b.y; acc[1][2] += a.y*b.z; acc[1][3] += a.y*b.w;
            acc[2][0] += a.z*b.x; acc[2][1] += a.z*b.y; acc[2][2] += a.z*b.z; acc[2][3] += a.z*b.w;
            acc[3][0] += a.w*b.x; acc[3][1] += a.w*b.y; acc[3][2] += a.w*b.z; acc[3][3] += a.w*b.w;
        }
        __syncthreads();
    }
    const float scale = 0.0625f;   // 1/sqrt(256)
    #pragma unroll
    for (int i = 0; i < 4; i++)
        #pragma unroll
        for (int j = 0; j < 4; j++)
            S[(size_t)(q0 + (ty << 2) + i) * LSEQ + c0 + (tx << 2) + j] = acc[i][j] * scale;
}

// ---------------------------------------------------------------------------
// Kernel 4: causal softmax, warp per row; also zeros above-diagonal residue
// inside the diagonal tile so PV can run unmasked.
// ---------------------------------------------------------------------------
__global__ void k_softmax() {
    int warp = threadIdx.x >> 5, lane = threadIdx.x & 31;
    int row = blockIdx.x * 8 + warp;
    int bh = row >> 10, q = row & (LSEQ - 1);
    float* Srow = g_S + (size_t)bh * LSEQ * LSEQ + (size_t)q * LSEQ;
    int len = q + 1;

    float m = -1e30f;
    for (int k = lane; k < len; k += 32) m = fmaxf(m, Srow[k]);
    #pragma unroll
    for (int o = 16; o; o >>= 1) m = fmaxf(m, __shfl_xor_sync(0xFFFFFFFFu, m, o));

    float s = 0.0f;
    for (int k = lane; k < len; k += 32) s += expf(Srow[k] - m);
    #pragma unroll
    for (int o = 16; o; o >>= 1) s += __shfl_xor_sync(0xFFFFFFFFu, s, o);

    float inv = 1.0f / s;
    for (int k = lane; k < len; k += 32) Srow[k] = expf(Srow[k] - m) * inv;

    int end = ((q >> 6) + 1) << 6;           // zero k in (q, tile_end)
    for (int k = q + 1 + lane; k < end; k += 32) Srow[k] = 0.0f;
}

// ---------------------------------------------------------------------------
// Kernel 5: O = P @ V, lower-triangle k-tiles only
// grid: (4 e-tiles, 16 qt, 32 bh), 256 threads
// ---------------------------------------------------------------------------
__global__ void k_pv(float* __restrict__ out) {
    int et = blockIdx.x, qt = blockIdx.y, bh = blockIdx.z;

    __shared__ float As[16][68];   // As[k][q]  (P)
    __shared__ float Bs[16][68];   // Bs[k][e]  (V)

    const float* P = g_S + (size_t)bh * LSEQ * LSEQ;
    const float* V = g_V + (size_t)bh * LSEQ * DIM;

    int tid = threadIdx.x;
    int tx = tid & 15, ty = tid >> 4;
    int q0 = qt * 64, e0 = et * 64;
    int kend = (qt + 1) * 64;

    float acc[4][4] = {};

    for (int k0 = 0; k0 < kend; k0 += 16) {
        #pragma unroll
        for (int i = 0; i < 4; i++) {
            int idx = tid + i * 256;
            int r = idx >> 4, c = idx & 15;
            As[c][r] = P[(size_t)(q0 + r) * LSEQ + k0 + c];
            int rb = idx >> 6, cb = idx & 63;
            Bs[rb][cb] = V[(size_t)(k0 + rb) * DIM + e0 + cb];
        }
        __syncthreads();
        #pragma unroll
        for (int k = 0; k < 16; k++) {
            float4 a = *(const float4*)&As[k][ty << 2];
            float4 b = *(const float4*)&Bs[k][tx << 2];
            acc[0][0] += a.x*b.x; acc[0][1] += a.x*b.y; acc[0][2] += a.x*b.z; acc[0][3] += a.x*b.w;
            acc[1][0] += a.y*b.x; acc[1][1] += a.y*b.y; acc[1][2] += a.y*b.z; acc[1][3] += a.y*b.w;
            acc[2][0] += a.z*b.x; acc[2][1] += a.z*b.y; acc[2][2] += a.z*b.z; acc[2][3] += a.z*b.w;
            acc[3][0] += a.w*b.x; acc[3][1] += a.w*b.y; acc[3][2] += a.w*b.z; acc[3][3] += a.w*b.w;
        }
        __syncthreads();
    }
    float* O = out + (size_t)bh * LSEQ * DIM;
    #pragma unroll
    for (int i = 0; i < 4; i++)
        #pragma unroll
        for (int j = 0; j < 4; j++)
            O[(size_t)(q0 + (ty << 2) + i) * DIM + e0 + (tx << 2) + j] = acc[i][j];
}

// ---------------------------------------------------------------------------
// Kernel 6: equivariant path. One thread per query; xi+PE staged in smem.
// grid: (8, 32), 128 threads
// ---------------------------------------------------------------------------
__global__ void k_equiv(const float* __restrict__ xi, float* __restrict__ out) {
    __shared__ float xs[LSEQ][3];
    int bh = blockIdx.y;
    int tid = threadIdx.x;
    const float inv23 = 0.0021544346900318843f;   // 10000^(-2/3)

    for (int l = tid; l < LSEQ; l += 128) {
        float fl = (float)l;
        const float* xr = xi + ((size_t)bh * LSEQ + l) * 3;
        xs[l][0] = xr[0] + sinf(fl);
        xs[l][1] = xr[1] + cosf(fl);
        xs[l][2] = xr[2] + sinf(fl * inv23);
    }
    __syncthreads();

    int q = blockIdx.x * 128 + tid;
    float qx = xs[q][0], qy = xs[q][1], qz = xs[q][2];

    float m = -1e30f, denom = 0.0f, wn = 0.0f;
    float n0 = 0.0f, n1 = 0.0f, n2 = 0.0f;

    for (int k = 0; k <= q; k++) {
        float dx = qx - xs[k][0], dy = qy - xs[k][1], dz = qz - xs[k][2];
        float sq = dx * dx + dy * dy + dz * dz;
        if (sq > m) {
            float sc = expf(m - sq);
            denom *= sc; wn *= sc; n0 *= sc; n1 *= sc; n2 *= sc;
            m = sq;
        }
        float e = expf(sq - m);
        denom += e;
        if (k != q) { wn += e; n0 += e * xs[k][0]; n1 += e * xs[k][1]; n2 += e * xs[k][2]; }
    }
    float invd = 1.0f / denom;
    float bw = 0.5f * wn * invd;                  // B_CONST * sum(mbeta)
    float* o = out + X_OFF + ((size_t)bh * LSEQ + q) * 3;
    o[0] = qx + 0.5f * n0 * invd - bw * qx;
    o[1] = qy + 0.5f * n1 * invd - bw * qy;
    o[2] = qz + 0.5f * n2 * invd - bw * qz;
}

// ---------------------------------------------------------------------------
// Kernel 7: edge_out = edge_attr + pe(L, 112)
// ---------------------------------------------------------------------------
__global__ void k_edge(const float* __restrict__ edge, float* __restrict__ out) {
    int idx = blockIdx.x * 256 + threadIdx.x;     // grid sized exactly
    int c = idx % EDGE_C;
    int l = (idx / EDGE_C) & (LSEQ - 1);
    float expo = (float)(c & ~1) * (1.0f / (float)EDGE_C);
    float p = powf(KAPPA, expo);
    float ang = (float)l / p;
    float pe = (c & 1) ? cosf(ang) : sinf(ang);
    out[E_OFF + idx] = edge[idx] + pe;
}

// ---------------------------------------------------------------------------
extern "C" void kernel_launch(void* const* d_in, const int* in_sizes, int n_in,
                              void* d_out, int out_size) {
    const float* theta = (const float*)d_in[0];
    const float* xi    = (const float*)d_in[1];
    const float* edge  = (const float*)d_in[2];
    const float* Wq    = (const float*)d_in[3];
    const float* Wk    = (const float*)d_in[4];
    const float* Wv    = (const float*)d_in[5];
    float* out = (float*)d_out;

    k_theta_pe<<<H_ELEMS / 256, 256>>>(theta);
    k_qkv<<<dim3(4, (BH * LSEQ) / 64, 3), 256>>>(Wq, Wk, Wv);
    k_scores<<<dim3(16, 16, BH), 256>>>();
    k_softmax<<<(BH * LSEQ) / 8, 256>>>();
    k_pv<<<dim3(4, 16, BH), 256>>>(out);
    k_equiv<<<dim3(8, BH), 128>>>(xi, out);
    k_edge<<<E_ELEMS / 256, 256>>>(edge, out);
}

// round 3
// speedup vs baseline: 1.8681x; 1.8681x over previous
#include <cuda_runtime.h>
#include <cuda_bf16.h>
#include <math.h>
#include <stdint.h>

typedef __nv_bfloat16 bf16;

// ---------------------------------------------------------------- constants
#define LSEQ 1024
#define DIM  256
#define BH   32          // B*N heads
#define EDGE_C 112
#define KAPPA 10000.0f

#define H_ELEMS  (BH * LSEQ * DIM)
#define X_ELEMS  (BH * LSEQ * 3)
#define E_ELEMS  (4 * LSEQ * EDGE_C)
#define X_OFF    H_ELEMS
#define E_OFF    (H_ELEMS + X_ELEMS)

// ---------------------------------------------------------------- scratch
__device__ __align__(16) bf16 g_TPh[H_ELEMS], g_TPl[H_ELEMS];
__device__ __align__(16) bf16 g_Wh[3 * DIM * DIM], g_Wl[3 * DIM * DIM];
__device__ __align__(16) bf16 g_Qh[H_ELEMS], g_Ql[H_ELEMS];
__device__ __align__(16) bf16 g_Kh[H_ELEMS], g_Kl[H_ELEMS];
__device__ __align__(16) bf16 g_Vh[H_ELEMS], g_Vl[H_ELEMS];
__device__ __align__(16) bf16 g_VTh[H_ELEMS], g_VTl[H_ELEMS];      // [bh][e][s]
__device__ __align__(16) float g_S[(size_t)BH * LSEQ * LSEQ];
__device__ __align__(16) bf16 g_Ph[(size_t)BH * LSEQ * LSEQ];
__device__ __align__(16) bf16 g_Pl[(size_t)BH * LSEQ * LSEQ];

__device__ __forceinline__ void split2(float v, bf16& h, bf16& l) {
    h = __float2bfloat16(v);
    l = __float2bfloat16(v - __bfloat162float(h));
}

// ---------------------------------------------------------------- MMA core
// D[m,n] += sum_k A[m,k] * B[n,k]  via m16n8k16 bf16 HMMA (sm_80 feature,
// compiles for plain sm_103 — tcgen05 does NOT).
#define MMA(acc, af, bf)                                                        \
    asm volatile(                                                               \
        "mma.sync.aligned.m16n8k16.row.col.f32.bf16.bf16.f32 "                  \
        "{%0,%1,%2,%3}, {%4,%5,%6,%7}, {%8,%9}, {%0,%1,%2,%3};"                 \
        : "+f"((acc)[0]), "+f"((acc)[1]), "+f"((acc)[2]), "+f"((acc)[3])        \
        : "r"((af)[0]), "r"((af)[1]), "r"((af)[2]), "r"((af)[3]),               \
          "r"((bf)[0]), "r"((bf)[1]))

#define KPAD 40   // 32-wide k-slice + 8 pad -> conflict-free b32 frag loads

struct Smem {
    bf16 Ah[128][KPAD], Al[128][KPAD], Bh[128][KPAD], Bl[128][KPAD];
};

// Load a 128x32 bf16 slice into smem. 256 threads, 2x uint4 each.
#define LDTILE(SM, GP, LD) do {                                                 \
    int _r = tid >> 2, _c = (tid & 3) * 8;                                      \
    *(uint4*)&SM[_r][_c]      = *(const uint4*)((GP) + (size_t)_r * (LD) + _c); \
    *(uint4*)&SM[_r + 64][_c] = *(const uint4*)((GP) + (size_t)(_r + 64) * (LD) + _c); \
} while (0)

// Block tile 128x128, 8 warps (2 m x 4 n), warp tile 64x32.
// 3-pass hi/lo split: hi*hi + hi*lo + lo*hi.
__device__ __forceinline__ void gemm_main(
    Smem& s,
    const bf16* __restrict__ Agh, const bf16* __restrict__ Agl, int lda,
    const bf16* __restrict__ Bgh, const bf16* __restrict__ Bgl, int ldb,
    int K, float acc[4][4][4], int tid)
{
    int wid = tid >> 5, lane = tid & 31;
    int wm = (wid >> 2) * 64, wn = (wid & 3) * 32;
    int gr = lane >> 2, t4 = lane & 3;

    for (int k0 = 0; k0 < K; k0 += 32) {
        LDTILE(s.Ah, Agh + k0, lda);
        LDTILE(s.Al, Agl + k0, lda);
        LDTILE(s.Bh, Bgh + k0, ldb);
        LDTILE(s.Bl, Bgl + k0, ldb);
        __syncthreads();
        #pragma unroll
        for (int kk = 0; kk < 32; kk += 16) {
            uint32_t Afh[4][4], Afl[4][4], Bfh[4][2], Bfl[4][2];
            #pragma unroll
            for (int mt = 0; mt < 4; mt++) {
                int r = wm + mt * 16 + gr, c = kk + 2 * t4;
                Afh[mt][0] = *(const uint32_t*)&s.Ah[r][c];
                Afh[mt][1] = *(const uint32_t*)&s.Ah[r + 8][c];
                Afh[mt][2] = *(const uint32_t*)&s.Ah[r][c + 8];
                Afh[mt][3] = *(const uint32_t*)&s.Ah[r + 8][c + 8];
                Afl[mt][0] = *(const uint32_t*)&s.Al[r][c];
                Afl[mt][1] = *(const uint32_t*)&s.Al[r + 8][c];
                Afl[mt][2] = *(const uint32_t*)&s.Al[r][c + 8];
                Afl[mt][3] = *(const uint32_t*)&s.Al[r + 8][c + 8];
            }
            #pragma unroll
            for (int nt = 0; nt < 4; nt++) {
                int n = wn + nt * 8 + gr, c = kk + 2 * t4;
                Bfh[nt][0] = *(const uint32_t*)&s.Bh[n][c];
                Bfh[nt][1] = *(const uint32_t*)&s.Bh[n][c + 8];
                Bfl[nt][0] = *(const uint32_t*)&s.Bl[n][c];
                Bfl[nt][1] = *(const uint32_t*)&s.Bl[n][c + 8];
            }
            #pragma unroll
            for (int mt = 0; mt < 4; mt++)
                #pragma unroll
                for (int nt = 0; nt < 4; nt++) {
                    MMA(acc[mt][nt], Afh[mt], Bfh[nt]);
                    MMA(acc[mt][nt], Afh[mt], Bfl[nt]);
                    MMA(acc[mt][nt], Afl[mt], Bfh[nt]);
                }
        }
        __syncthreads();
    }
}

// ---------------------------------------------------------------- prep
__global__ void k_prep_w(const float* __restrict__ Wq, const float* __restrict__ Wk,
                         const float* __restrict__ Wv) {
    int idx = blockIdx.x * 256 + threadIdx.x;
    int mat = idx >> 16, off = idx & 65535;
    const float* W = (mat == 0) ? Wq : (mat == 1) ? Wk : Wv;
    split2(W[off], g_Wh[idx], g_Wl[idx]);
}

__global__ void k_theta_pe(const float* __restrict__ theta) {
    int idx = blockIdx.x * 256 + threadIdx.x;
    int i = idx & (DIM - 1);
    int l = (idx >> 8) & (LSEQ - 1);
    float expo = (float)(i & ~1) * (1.0f / (float)DIM);
    float ang = (float)l / powf(KAPPA, expo);
    float pe = (i & 1) ? cosf(ang) : sinf(ang);
    split2(theta[idx] + pe, g_TPh[idx], g_TPl[idx]);
}

// ---------------------------------------------------------------- QKV
// Out[m,e] = sum_d TP[m,d] * W[e,d].  grid (2 et, 256 mt, 3 mat), 256 thr
__global__ void __launch_bounds__(256) k_qkv_mma() {
    __shared__ Smem s;
    int tid = threadIdx.x;
    int e0 = blockIdx.x * 128, m0 = blockIdx.y * 128, mat = blockIdx.z;

    float acc[4][4][4] = {};
    gemm_main(s, g_TPh + (size_t)m0 * DIM, g_TPl + (size_t)m0 * DIM, DIM,
              g_Wh + (size_t)mat * 65536 + (size_t)e0 * DIM,
              g_Wl + (size_t)mat * 65536 + (size_t)e0 * DIM, DIM,
              DIM, acc, tid);

    bf16 *oh, *ol;
    if (mat == 0)      { oh = g_Qh; ol = g_Ql; }
    else if (mat == 1) { oh = g_Kh; ol = g_Kl; }
    else               { oh = g_Vh; ol = g_Vl; }
    int wid = tid >> 5, lane = tid & 31;
    int wm = (wid >> 2) * 64, wn = (wid & 3) * 32;
    int gr = lane >> 2, t4 = lane & 3;
    #pragma unroll
    for (int mt = 0; mt < 4; mt++)
        #pragma unroll
        for (int nt = 0; nt < 4; nt++)
            #pragma unroll
            for (int half = 0; half < 2; half++) {
                int r = m0 + wm + mt * 16 + gr + half * 8;
                int c = e0 + wn + nt * 8 + 2 * t4;
                __nv_bfloat162 h2, l2;
                split2(acc[mt][nt][half * 2],     h2.x, l2.x);
                split2(acc[mt][nt][half * 2 + 1], h2.y, l2.y);
                *(uint32_t*)&oh[(size_t)r * DIM + c] = *(uint32_t*)&h2;
                *(uint32_t*)&ol[(size_t)r * DIM + c] = *(uint32_t*)&l2;
            }
}

// ---------------------------------------------------------------- V transpose
__global__ void k_vt() {
    __shared__ bf16 th[32][33], tl[32][33];
    int s0 = blockIdx.x * 32, e0 = blockIdx.y * 32, bh = blockIdx.z;
    int tx = threadIdx.x, ty = threadIdx.y;
    #pragma unroll
    for (int j = 0; j < 4; j++) {
        int sr = s0 + ty + j * 8;
        size_t src = ((size_t)bh * LSEQ + sr) * DIM + e0 + tx;
        th[ty + j * 8][tx] = g_Vh[src];
        tl[ty + j * 8][tx] = g_Vl[src];
    }
    __syncthreads();
    #pragma unroll
    for (int j = 0; j < 4; j++) {
        int e = e0 + ty + j * 8;
        size_t dst = ((size_t)bh * DIM + e) * LSEQ + s0 + tx;
        g_VTh[dst] = th[tx][ty + j * 8];
        g_VTl[dst] = tl[tx][ty + j * 8];
    }
}

// ---------------------------------------------------------------- scores
// S[q,k] = (Q.K)/16, lower tiles.  grid (8 kt, 8 qt, 32 bh), 256 thr
__global__ void __launch_bounds__(256) k_scores_mma() {
    int kt = blockIdx.x, qt = blockIdx.y, bh = blockIdx.z;
    if (kt > qt) return;
    __shared__ Smem s;
    int tid = threadIdx.x;
    int q0 = qt * 128, c0 = kt * 128;
    size_t qb = ((size_t)bh * LSEQ + q0) * DIM;
    size_t kb = ((size_t)bh * LSEQ + c0) * DIM;

    float acc[4][4][4] = {};
    gemm_main(s, g_Qh + qb, g_Ql + qb, DIM, g_Kh + kb, g_Kl + kb, DIM,
              DIM, acc, tid);

    int wid = tid >> 5, lane = tid & 31;
    int wm = (wid >> 2) * 64, wn = (wid & 3) * 32;
    int gr = lane >> 2, t4 = lane & 3;
    float* S = g_S + (size_t)bh * LSEQ * LSEQ;
    #pragma unroll
    for (int mt = 0; mt < 4; mt++)
        #pragma unroll
        for (int nt = 0; nt < 4; nt++)
            #pragma unroll
            for (int half = 0; half < 2; half++) {
                int r = q0 + wm + mt * 16 + gr + half * 8;
                int c = c0 + wn + nt * 8 + 2 * t4;
                float2 v = make_float2(acc[mt][nt][half * 2] * 0.0625f,
                                       acc[mt][nt][half * 2 + 1] * 0.0625f);
                *(float2*)&S[(size_t)r * LSEQ + c] = v;
            }
}

// ---------------------------------------------------------------- softmax
__global__ void k_softmax() {
    int warp = threadIdx.x >> 5, lane = threadIdx.x & 31;
    int row = blockIdx.x * 8 + warp;
    int bh = row >> 10, q = row & (LSEQ - 1);
    size_t base = (size_t)bh * LSEQ * LSEQ + (size_t)q * LSEQ;
    const float* Srow = g_S + base;
    int len = q + 1;

    float m = -1e30f;
    for (int k = lane; k < len; k += 32) m = fmaxf(m, Srow[k]);
    #pragma unroll
    for (int o = 16; o; o >>= 1) m = fmaxf(m, __shfl_xor_sync(0xFFFFFFFFu, m, o));
    float ssum = 0.0f;
    for (int k = lane; k < len; k += 32) ssum += expf(Srow[k] - m);
    #pragma unroll
    for (int o = 16; o; o >>= 1) ssum += __shfl_xor_sync(0xFFFFFFFFu, ssum, o);
    float inv = 1.0f / ssum;
    for (int k = lane; k < len; k += 32) {
        float p = expf(Srow[k] - m) * inv;
        bf16 h, l; split2(p, h, l);
        g_Ph[base + k] = h; g_Pl[base + k] = l;
    }
    int end = ((q >> 7) + 1) << 7;
    for (int k = q + 1 + lane; k < end; k += 32) {
        g_Ph[base + k] = __float2bfloat16(0.0f);
        g_Pl[base + k] = __float2bfloat16(0.0f);
    }
}

// ---------------------------------------------------------------- PV
// O[q,e] = sum_k P[q,k] * VT[e,k].  grid (2 et, 8 qt, 32 bh), 256 thr
__global__ void __launch_bounds__(256) k_pv_mma(float* __restrict__ out) {
    int et = blockIdx.x, qt = blockIdx.y, bh = blockIdx.z;
    __shared__ Smem s;
    int tid = threadIdx.x;
    int q0 = qt * 128, e0 = et * 128;
    size_t pb = (size_t)bh * LSEQ * LSEQ + (size_t)q0 * LSEQ;
    size_t vb = ((size_t)bh * DIM + e0) * LSEQ;

    float acc[4][4][4] = {};
    gemm_main(s, g_Ph + pb, g_Pl + pb, LSEQ, g_VTh + vb, g_VTl + vb, LSEQ,
              (qt + 1) * 128, acc, tid);

    int wid = tid >> 5, lane = tid & 31;
    int wm = (wid >> 2) * 64, wn = (wid & 3) * 32;
    int gr = lane >> 2, t4 = lane & 3;
    float* O = out + ((size_t)bh * LSEQ + q0) * DIM + e0;
    #pragma unroll
    for (int mt = 0; mt < 4; mt++)
        #pragma unroll
        for (int nt = 0; nt < 4; nt++)
            #pragma unroll
            for (int half = 0; half < 2; half++) {
                int r = wm + mt * 16 + gr + half * 8;
                int c = wn + nt * 8 + 2 * t4;
                float2 v = make_float2(acc[mt][nt][half * 2],
                                       acc[mt][nt][half * 2 + 1]);
                *(float2*)&O[(size_t)r * DIM + c] = v;
            }
}

// ---------------------------------------------------------------- equivariant
__global__ void k_equiv(const float* __restrict__ xi, float* __restrict__ out) {
    __shared__ float xs[LSEQ][3];
    int bh = blockIdx.y;
    int tid = threadIdx.x;
    const float inv23 = 0.0021544346900318843f;

    for (int l = tid; l < LSEQ; l += 128) {
        float fl = (float)l;
        const float* xr = xi + ((size_t)bh * LSEQ + l) * 3;
        xs[l][0] = xr[0] + sinf(fl);
        xs[l][1] = xr[1] + cosf(fl);
        xs[l][2] = xr[2] + sinf(fl * inv23);
    }
    __syncthreads();

    int q = blockIdx.x * 128 + tid;
    float qx = xs[q][0], qy = xs[q][1], qz = xs[q][2];
    float m = -1e30f, denom = 0.0f, wn = 0.0f;
    float n0 = 0.0f, n1 = 0.0f, n2 = 0.0f;
    for (int k = 0; k <= q; k++) {
        float dx = qx - xs[k][0], dy = qy - xs[k][1], dz = qz - xs[k][2];
        float sq = dx * dx + dy * dy + dz * dz;
        if (sq > m) {
            float sc = expf(m - sq);
            denom *= sc; wn *= sc; n0 *= sc; n1 *= sc; n2 *= sc;
            m = sq;
        }
        float e = expf(sq - m);
        denom += e;
        if (k != q) { wn += e; n0 += e * xs[k][0]; n1 += e * xs[k][1]; n2 += e * xs[k][2]; }
    }
    float invd = 1.0f / denom;
    float bw = 0.5f * wn * invd;
    float* o = out + X_OFF + ((size_t)bh * LSEQ + q) * 3;
    o[0] = qx + 0.5f * n0 * invd - bw * qx;
    o[1] = qy + 0.5f * n1 * invd - bw * qy;
    o[2] = qz + 0.5f * n2 * invd - bw * qz;
}

// ---------------------------------------------------------------- edge
__global__ void k_edge(const float* __restrict__ edge, float* __restrict__ out) {
    int idx = blockIdx.x * 256 + threadIdx.x;
    int c = idx % EDGE_C;
    int l = (idx / EDGE_C) & (LSEQ - 1);
    float expo = (float)(c & ~1) * (1.0f / (float)EDGE_C);
    float ang = (float)l / powf(KAPPA, expo);
    float pe = (c & 1) ? cosf(ang) : sinf(ang);
    out[E_OFF + idx] = edge[idx] + pe;
}

// ----------------------------------------------------------------------------
extern "C" void kernel_launch(void* const* d_in, const int* in_sizes, int n_in,
                              void* d_out, int out_size) {
    const float* theta = (const float*)d_in[0];
    const float* xi    = (const float*)d_in[1];
    const float* edge  = (const float*)d_in[2];
    const float* Wq    = (const float*)d_in[3];
    const float* Wk    = (const float*)d_in[4];
    const float* Wv    = (const float*)d_in[5];
    float* out = (float*)d_out;

    k_prep_w<<<(3 * DIM * DIM) / 256, 256>>>(Wq, Wk, Wv);
    k_theta_pe<<<H_ELEMS / 256, 256>>>(theta);
    k_qkv_mma<<<dim3(2, 256, 3), 256>>>();
    k_vt<<<dim3(32, 8, 32), dim3(32, 8)>>>();
    k_scores_mma<<<dim3(8, 8, BH), 256>>>();
    k_softmax<<<(BH * LSEQ) / 8, 256>>>();
    k_pv_mma<<<dim3(2, 8, BH), 256>>>(out);
    k_equiv<<<dim3(8, BH), 128>>>(xi, out);
    k_edge<<<E_ELEMS / 256, 256>>>(edge, out);
}

// round 4
// speedup vs baseline: 2.0002x; 1.0707x over previous
#include <cuda_runtime.h>
#include <cuda_bf16.h>
#include <math.h>
#include <stdint.h>

typedef __nv_bfloat16 bf16;

// ---------------------------------------------------------------- constants
#define LSEQ 1024
#define DIM  256
#define BH   32          // B*N heads
#define EDGE_C 112
#define KAPPA 10000.0f

#define H_ELEMS  (BH * LSEQ * DIM)
#define X_ELEMS  (BH * LSEQ * 3)
#define E_ELEMS  (4 * LSEQ * EDGE_C)
#define X_OFF    H_ELEMS
#define E_OFF    (H_ELEMS + X_ELEMS)

// ---------------------------------------------------------------- scratch
__device__ __align__(16) bf16 g_TPh[H_ELEMS], g_TPl[H_ELEMS];
__device__ __align__(16) bf16 g_Wh[3 * DIM * DIM], g_Wl[3 * DIM * DIM];
__device__ __align__(16) bf16 g_Qh[H_ELEMS], g_Ql[H_ELEMS];
__device__ __align__(16) bf16 g_Kh[H_ELEMS], g_Kl[H_ELEMS];
__device__ __align__(16) bf16 g_Vh[H_ELEMS], g_Vl[H_ELEMS];
__device__ __align__(16) bf16 g_VTh[H_ELEMS], g_VTl[H_ELEMS];      // [bh][e][s]
__device__ __align__(16) float g_S[(size_t)BH * LSEQ * LSEQ];
__device__ __align__(16) bf16 g_Ph[(size_t)BH * LSEQ * LSEQ];
__device__ __align__(16) bf16 g_Pl[(size_t)BH * LSEQ * LSEQ];

__device__ __forceinline__ void split2(float v, bf16& h, bf16& l) {
    h = __float2bfloat16(v);
    l = __float2bfloat16(v - __bfloat162float(h));
}

// ---------------------------------------------------------------- MMA core
#define MMA(acc, af, bf)                                                        \
    asm volatile(                                                               \
        "mma.sync.aligned.m16n8k16.row.col.f32.bf16.bf16.f32 "                  \
        "{%0,%1,%2,%3}, {%4,%5,%6,%7}, {%8,%9}, {%0,%1,%2,%3};"                 \
        : "+f"((acc)[0]), "+f"((acc)[1]), "+f"((acc)[2]), "+f"((acc)[3])        \
        : "r"((af)[0]), "r"((af)[1]), "r"((af)[2]), "r"((af)[3]),               \
          "r"((bf)[0]), "r"((bf)[1]))

#define KPAD 40   // 32 k + 8 pad: 80B row stride (16B aligned for cp.async)

struct Stage {
    bf16 Ah[128][KPAD], Al[128][KPAD], Bh[128][KPAD], Bl[128][KPAD];
};
#define SMEM_DYN (2 * sizeof(Stage))   // 81920 B

__device__ __forceinline__ void cp16(void* dst, const void* src) {
    uint32_t d = (uint32_t)__cvta_generic_to_shared(dst);
    asm volatile("cp.async.cg.shared.global [%0], [%1], 16;" :: "r"(d), "l"(src));
}
#define CP_COMMIT() asm volatile("cp.async.commit_group;" ::: "memory")
#define CP_WAIT1()  asm volatile("cp.async.wait_group 1;" ::: "memory")
#define CP_WAIT0()  asm volatile("cp.async.wait_group 0;" ::: "memory")

// Async-stage one 128x32 bf16 slice (256 threads, 2 x 16B each).
#define LDTA(SM, GP, LD) do {                                                   \
    int _r = tid >> 2, _c = (tid & 3) * 8;                                      \
    cp16(&SM[_r][_c],      (GP) + (size_t)_r * (LD) + _c);                      \
    cp16(&SM[_r + 64][_c], (GP) + (size_t)(_r + 64) * (LD) + _c);               \
} while (0)

#define LDSTAGE(ST, K0) do {                                                    \
    LDTA((ST).Ah, Agh + (K0), lda);                                             \
    LDTA((ST).Al, Agl + (K0), lda);                                             \
    LDTA((ST).Bh, Bgh + (K0), ldb);                                             \
    LDTA((ST).Bl, Bgl + (K0), ldb);                                             \
    CP_COMMIT();                                                                \
} while (0)

// Block tile 128x128, 8 warps (2m x 4n), warp tile 64x32, K-step 32,
// cp.async double-buffered.  3-pass hi/lo split.
__device__ __forceinline__ void gemm_main(
    Stage* stg,
    const bf16* __restrict__ Agh, const bf16* __restrict__ Agl, int lda,
    const bf16* __restrict__ Bgh, const bf16* __restrict__ Bgl, int ldb,
    int K, float acc[4][4][4], int tid)
{
    int wid = tid >> 5, lane = tid & 31;
    int wm = (wid >> 2) * 64, wn = (wid & 3) * 32;
    int gr = lane >> 2, t4 = lane & 3;
    int nst = K >> 5;

    LDSTAGE(stg[0], 0);

    for (int c = 0; c < nst; c++) {
        if (c + 1 < nst) { LDSTAGE(stg[(c + 1) & 1], (c + 1) * 32); CP_WAIT1(); }
        else             { CP_WAIT0(); }
        __syncthreads();
        Stage& s = stg[c & 1];
        #pragma unroll
        for (int kk = 0; kk < 32; kk += 16) {
            uint32_t Afh[4][4], Afl[4][4], Bfh[4][2], Bfl[4][2];
            #pragma unroll
            for (int mt = 0; mt < 4; mt++) {
                int r = wm + mt * 16 + gr, cc = kk + 2 * t4;
                Afh[mt][0] = *(const uint32_t*)&s.Ah[r][cc];
                Afh[mt][1] = *(const uint32_t*)&s.Ah[r + 8][cc];
                Afh[mt][2] = *(const uint32_t*)&s.Ah[r][cc + 8];
                Afh[mt][3] = *(const uint32_t*)&s.Ah[r + 8][cc + 8];
                Afl[mt][0] = *(const uint32_t*)&s.Al[r][cc];
                Afl[mt][1] = *(const uint32_t*)&s.Al[r + 8][cc];
                Afl[mt][2] = *(const uint32_t*)&s.Al[r][cc + 8];
                Afl[mt][3] = *(const uint32_t*)&s.Al[r + 8][cc + 8];
            }
            #pragma unroll
            for (int nt = 0; nt < 4; nt++) {
                int n = wn + nt * 8 + gr, cc = kk + 2 * t4;
                Bfh[nt][0] = *(const uint32_t*)&s.Bh[n][cc];
                Bfh[nt][1] = *(const uint32_t*)&s.Bh[n][cc + 8];
                Bfl[nt][0] = *(const uint32_t*)&s.Bl[n][cc];
                Bfl[nt][1] = *(const uint32_t*)&s.Bl[n][cc + 8];
            }
            #pragma unroll
            for (int mt = 0; mt < 4; mt++)
                #pragma unroll
                for (int nt = 0; nt < 4; nt++) {
                    MMA(acc[mt][nt], Afh[mt], Bfh[nt]);
                    MMA(acc[mt][nt], Afh[mt], Bfl[nt]);
                    MMA(acc[mt][nt], Afl[mt], Bfh[nt]);
                }
        }
        __syncthreads();
    }
}

// ---------------------------------------------------------------- prep
__global__ void k_prep_w(const float* __restrict__ Wq, const float* __restrict__ Wk,
                         const float* __restrict__ Wv) {
    int idx = blockIdx.x * 256 + threadIdx.x;
    int mat = idx >> 16, off = idx & 65535;
    const float* W = (mat == 0) ? Wq : (mat == 1) ? Wk : Wv;
    split2(W[off], g_Wh[idx], g_Wl[idx]);
}

__global__ void k_theta_pe(const float* __restrict__ theta) {
    int idx = blockIdx.x * 256 + threadIdx.x;
    int i = idx & (DIM - 1);
    int l = (idx >> 8) & (LSEQ - 1);
    float expo = (float)(i & ~1) * (1.0f / (float)DIM);
    float ang = (float)l / powf(KAPPA, expo);
    float pe = (i & 1) ? cosf(ang) : sinf(ang);
    split2(theta[idx] + pe, g_TPh[idx], g_TPl[idx]);
}

// ---------------------------------------------------------------- QKV
__global__ void __launch_bounds__(256) k_qkv_mma() {
    extern __shared__ char smraw[];
    Stage* stg = reinterpret_cast<Stage*>(smraw);
    int tid = threadIdx.x;
    int e0 = blockIdx.x * 128, m0 = blockIdx.y * 128, mat = blockIdx.z;

    float acc[4][4][4] = {};
    gemm_main(stg, g_TPh + (size_t)m0 * DIM, g_TPl + (size_t)m0 * DIM, DIM,
              g_Wh + (size_t)mat * 65536 + (size_t)e0 * DIM,
              g_Wl + (size_t)mat * 65536 + (size_t)e0 * DIM, DIM,
              DIM, acc, tid);

    bf16 *oh, *ol;
    if (mat == 0)      { oh = g_Qh; ol = g_Ql; }
    else if (mat == 1) { oh = g_Kh; ol = g_Kl; }
    else               { oh = g_Vh; ol = g_Vl; }
    int wid = tid >> 5, lane = tid & 31;
    int wm = (wid >> 2) * 64, wn = (wid & 3) * 32;
    int gr = lane >> 2, t4 = lane & 3;
    #pragma unroll
    for (int mt = 0; mt < 4; mt++)
        #pragma unroll
        for (int nt = 0; nt < 4; nt++)
            #pragma unroll
            for (int half = 0; half < 2; half++) {
                int r = m0 + wm + mt * 16 + gr + half * 8;
                int c = e0 + wn + nt * 8 + 2 * t4;
                __nv_bfloat162 h2, l2;
                split2(acc[mt][nt][half * 2],     h2.x, l2.x);
                split2(acc[mt][nt][half * 2 + 1], h2.y, l2.y);
                *(uint32_t*)&oh[(size_t)r * DIM + c] = *(uint32_t*)&h2;
                *(uint32_t*)&ol[(size_t)r * DIM + c] = *(uint32_t*)&l2;
            }
}

// ---------------------------------------------------------------- V transpose
__global__ void k_vt() {
    __shared__ bf16 th[32][33], tl[32][33];
    int s0 = blockIdx.x * 32, e0 = blockIdx.y * 32, bh = blockIdx.z;
    int tx = threadIdx.x, ty = threadIdx.y;
    #pragma unroll
    for (int j = 0; j < 4; j++) {
        int sr = s0 + ty + j * 8;
        size_t src = ((size_t)bh * LSEQ + sr) * DIM + e0 + tx;
        th[ty + j * 8][tx] = g_Vh[src];
        tl[ty + j * 8][tx] = g_Vl[src];
    }
    __syncthreads();
    #pragma unroll
    for (int j = 0; j < 4; j++) {
        int e = e0 + ty + j * 8;
        size_t dst = ((size_t)bh * DIM + e) * LSEQ + s0 + tx;
        g_VTh[dst] = th[tx][ty + j * 8];
        g_VTl[dst] = tl[tx][ty + j * 8];
    }
}

// ---------------------------------------------------------------- scores
__global__ void __launch_bounds__(256) k_scores_mma() {
    int kt = blockIdx.x, qt = blockIdx.y, bh = blockIdx.z;
    if (kt > qt) return;
    extern __shared__ char smraw[];
    Stage* stg = reinterpret_cast<Stage*>(smraw);
    int tid = threadIdx.x;
    int q0 = qt * 128, c0 = kt * 128;
    size_t qb = ((size_t)bh * LSEQ + q0) * DIM;
    size_t kb = ((size_t)bh * LSEQ + c0) * DIM;

    float acc[4][4][4] = {};
    gemm_main(stg, g_Qh + qb, g_Ql + qb, DIM, g_Kh + kb, g_Kl + kb, DIM,
              DIM, acc, tid);

    int wid = tid >> 5, lane = tid & 31;
    int wm = (wid >> 2) * 64, wn = (wid & 3) * 32;
    int gr = lane >> 2, t4 = lane & 3;
    float* S = g_S + (size_t)bh * LSEQ * LSEQ;
    #pragma unroll
    for (int mt = 0; mt < 4; mt++)
        #pragma unroll
        for (int nt = 0; nt < 4; nt++)
            #pragma unroll
            for (int half = 0; half < 2; half++) {
                int r = q0 + wm + mt * 16 + gr + half * 8;
                int c = c0 + wn + nt * 8 + 2 * t4;
                float2 v = make_float2(acc[mt][nt][half * 2] * 0.0625f,
                                       acc[mt][nt][half * 2 + 1] * 0.0625f);
                *(float2*)&S[(size_t)r * LSEQ + c] = v;
            }
}

// ---------------------------------------------------------------- softmax
__global__ void k_softmax() {
    int warp = threadIdx.x >> 5, lane = threadIdx.x & 31;
    int row = blockIdx.x * 8 + warp;
    int bh = row >> 10, q = row & (LSEQ - 1);
    size_t base = (size_t)bh * LSEQ * LSEQ + (size_t)q * LSEQ;
    const float* Srow = g_S + base;
    int len = q + 1;

    float m = -1e30f;
    for (int k = lane; k < len; k += 32) m = fmaxf(m, Srow[k]);
    #pragma unroll
    for (int o = 16; o; o >>= 1) m = fmaxf(m, __shfl_xor_sync(0xFFFFFFFFu, m, o));
    float ssum = 0.0f;
    for (int k = lane; k < len; k += 32) ssum += expf(Srow[k] - m);
    #pragma unroll
    for (int o = 16; o; o >>= 1) ssum += __shfl_xor_sync(0xFFFFFFFFu, ssum, o);
    float inv = 1.0f / ssum;
    for (int k = lane; k < len; k += 32) {
        float p = expf(Srow[k] - m) * inv;
        bf16 h, l; split2(p, h, l);
        g_Ph[base + k] = h; g_Pl[base + k] = l;
    }
    int end = ((q >> 7) + 1) << 7;
    for (int k = q + 1 + lane; k < end; k += 32) {
        g_Ph[base + k] = __float2bfloat16(0.0f);
        g_Pl[base + k] = __float2bfloat16(0.0f);
    }
}

// ---------------------------------------------------------------- PV
__global__ void __launch_bounds__(256) k_pv_mma(float* __restrict__ out) {
    int et = blockIdx.x, qt = blockIdx.y, bh = blockIdx.z;
    extern __shared__ char smraw[];
    Stage* stg = reinterpret_cast<Stage*>(smraw);
    int tid = threadIdx.x;
    int q0 = qt * 128, e0 = et * 128;
    size_t pb = (size_t)bh * LSEQ * LSEQ + (size_t)q0 * LSEQ;
    size_t vb = ((size_t)bh * DIM + e0) * LSEQ;

    float acc[4][4][4] = {};
    gemm_main(stg, g_Ph + pb, g_Pl + pb, LSEQ, g_VTh + vb, g_VTl + vb, LSEQ,
              (qt + 1) * 128, acc, tid);

    int wid = tid >> 5, lane = tid & 31;
    int wm = (wid >> 2) * 64, wn = (wid & 3) * 32;
    int gr = lane >> 2, t4 = lane & 3;
    float* O = out + ((size_t)bh * LSEQ + q0) * DIM + e0;
    #pragma unroll
    for (int mt = 0; mt < 4; mt++)
        #pragma unroll
        for (int nt = 0; nt < 4; nt++)
            #pragma unroll
            for (int half = 0; half < 2; half++) {
                int r = wm + mt * 16 + gr + half * 8;
                int c = wn + nt * 8 + 2 * t4;
                float2 v = make_float2(acc[mt][nt][half * 2],
                                       acc[mt][nt][half * 2 + 1]);
                *(float2*)&O[(size_t)r * DIM + c] = v;
            }
}

// ---------------------------------------------------------------- equivariant
__global__ void k_equiv(const float* __restrict__ xi, float* __restrict__ out) {
    __shared__ float xs[LSEQ][3];
    int bh = blockIdx.y;
    int tid = threadIdx.x;
    const float inv23 = 0.0021544346900318843f;

    for (int l = tid; l < LSEQ; l += 128) {
        float fl = (float)l;
        const float* xr = xi + ((size_t)bh * LSEQ + l) * 3;
        xs[l][0] = xr[0] + sinf(fl);
        xs[l][1] = xr[1] + cosf(fl);
        xs[l][2] = xr[2] + sinf(fl * inv23);
    }
    __syncthreads();

    int q = blockIdx.x * 128 + tid;
    float qx = xs[q][0], qy = xs[q][1], qz = xs[q][2];
    float m = -1e30f, denom = 0.0f, wn = 0.0f;
    float n0 = 0.0f, n1 = 0.0f, n2 = 0.0f;
    for (int k = 0; k <= q; k++) {
        float dx = qx - xs[k][0], dy = qy - xs[k][1], dz = qz - xs[k][2];
        float sq = dx * dx + dy * dy + dz * dz;
        if (sq > m) {
            float sc = expf(m - sq);
            denom *= sc; wn *= sc; n0 *= sc; n1 *= sc; n2 *= sc;
            m = sq;
        }
        float e = expf(sq - m);
        denom += e;
        if (k != q) { wn += e; n0 += e * xs[k][0]; n1 += e * xs[k][1]; n2 += e * xs[k][2]; }
    }
    float invd = 1.0f / denom;
    float bw = 0.5f * wn * invd;
    float* o = out + X_OFF + ((size_t)bh * LSEQ + q) * 3;
    o[0] = qx + 0.5f * n0 * invd - bw * qx;
    o[1] = qy + 0.5f * n1 * invd - bw * qy;
    o[2] = qz + 0.5f * n2 * invd - bw * qz;
}

// ---------------------------------------------------------------- edge
__global__ void k_edge(const float* __restrict__ edge, float* __restrict__ out) {
    int idx = blockIdx.x * 256 + threadIdx.x;
    int c = idx % EDGE_C;
    int l = (idx / EDGE_C) & (LSEQ - 1);
    float expo = (float)(c & ~1) * (1.0f / (float)EDGE_C);
    float ang = (float)l / powf(KAPPA, expo);
    float pe = (c & 1) ? cosf(ang) : sinf(ang);
    out[E_OFF + idx] = edge[idx] + pe;
}

// ----------------------------------------------------------------------------
extern "C" void kernel_launch(void* const* d_in, const int* in_sizes, int n_in,
                              void* d_out, int out_size) {
    const float* theta = (const float*)d_in[0];
    const float* xi    = (const float*)d_in[1];
    const float* edge  = (const float*)d_in[2];
    const float* Wq    = (const float*)d_in[3];
    const float* Wk    = (const float*)d_in[4];
    const float* Wv    = (const float*)d_in[5];
    float* out = (float*)d_out;

    static bool attr_done = false;
    if (!attr_done) {
        cudaFuncSetAttribute(k_qkv_mma,    cudaFuncAttributeMaxDynamicSharedMemorySize, (int)SMEM_DYN);
        cudaFuncSetAttribute(k_scores_mma, cudaFuncAttributeMaxDynamicSharedMemorySize, (int)SMEM_DYN);
        cudaFuncSetAttribute(k_pv_mma,     cudaFuncAttributeMaxDynamicSharedMemorySize, (int)SMEM_DYN);
        attr_done = true;
    }

    k_prep_w<<<(3 * DIM * DIM) / 256, 256>>>(Wq, Wk, Wv);
    k_theta_pe<<<H_ELEMS / 256, 256>>>(theta);
    k_qkv_mma<<<dim3(2, 256, 3), 256, SMEM_DYN>>>();
    k_vt<<<dim3(32, 8, 32), dim3(32, 8)>>>();
    k_scores_mma<<<dim3(8, 8, BH), 256, SMEM_DYN>>>();
    k_softmax<<<(BH * LSEQ) / 8, 256>>>();
    k_pv_mma<<<dim3(2, 8, BH), 256, SMEM_DYN>>>(out);
    k_equiv<<<dim3(8, BH), 128>>>(xi, out);
    k_edge<<<E_ELEMS / 256, 256>>>(edge, out);
}